// round 1
// baseline (speedup 1.0000x reference)
#include <cuda_runtime.h>
#include <cuda_bf16.h>

#define NBS 100000
#define NGS 20000
#define EL  1000000
#define EX  200000

// ---------------- scratch (static device globals; no allocation) ----------------
__device__ float g_hb[NBS * 64];
__device__ float g_hg[NGS * 64];
__device__ float g_outb[NBS * 192];   // [self | line-msg | b2g-msg]
__device__ float g_outg[NGS * 128];   // [self | g2b-msg]
__device__ float g_aggL[NBS * 64];
__device__ float g_aggG[NBS * 64];
__device__ float g_aggB[NGS * 64];
__device__ float g_invL[NBS], g_invG[NBS], g_invB[NGS];
__device__ int   g_cntL[NBS], g_cntG[NBS], g_cntB[NGS];
__device__ float g_pool[128];

// ---------------- init / counts ----------------
__global__ void k_zero_init() {
    int i = blockIdx.x * blockDim.x + threadIdx.x;
    if (i < NBS) { g_cntL[i] = 0; g_cntG[i] = 0; }
    if (i < NGS) g_cntB[i] = 0;
    if (i < 128) g_pool[i] = 0.f;
}

__global__ void k_count(const int* __restrict__ dst, int n, int sel) {
    int i = blockIdx.x * blockDim.x + threadIdx.x;
    if (i >= n) return;
    int* cnt = (sel == 0) ? g_cntL : (sel == 1) ? g_cntG : g_cntB;
    atomicAdd(&cnt[dst[i]], 1);
}

__global__ void k_inv() {
    int i = blockIdx.x * blockDim.x + threadIdx.x;
    if (i < NBS) {
        g_invL[i] = 1.f / (float)max(g_cntL[i], 1);
        g_invG[i] = 1.f / (float)max(g_cntG[i], 1);
    }
    if (i < NGS) g_invB[i] = 1.f / (float)max(g_cntB[i], 1);
}

// ---------------- fused GEMMs ----------------
// bus: out[row, 0:64]=x@Wsb+bsb, [64:128]=x@Wl, [128:192]=x@Wb2g
__global__ void __launch_bounds__(256) k_gemm_bus(
    const float* __restrict__ xin,
    const float* __restrict__ Wsb, const float* __restrict__ Wl,
    const float* __restrict__ Wb2g, const float* __restrict__ bsb)
{
    __shared__ float sW[64 * 192];
    for (int idx = threadIdx.x; idx < 64 * 192; idx += 256) {
        int k = idx / 192, j = idx % 192;
        float v;
        if (j < 64)       v = Wsb[k * 64 + j];
        else if (j < 128) v = Wl[k * 64 + (j - 64)];
        else              v = Wb2g[k * 64 + (j - 128)];
        sW[idx] = v;
    }
    __syncthreads();
    int row = blockIdx.x * 256 + threadIdx.x;
    if (row >= NBS) return;
    const float* xp = xin ? xin : g_hb;
    float xr[64];
    const float4* x4 = (const float4*)(xp + (size_t)row * 64);
#pragma unroll
    for (int i = 0; i < 16; i++) ((float4*)xr)[i] = x4[i];
    float4* outr = (float4*)(g_outb + (size_t)row * 192);
    for (int j4 = 0; j4 < 48; j4++) {
        int j = j4 * 4;
        float4 acc;
        if (j < 64) acc = make_float4(__ldg(&bsb[j]), __ldg(&bsb[j + 1]),
                                      __ldg(&bsb[j + 2]), __ldg(&bsb[j + 3]));
        else acc = make_float4(0.f, 0.f, 0.f, 0.f);
#pragma unroll
        for (int k = 0; k < 64; k++) {
            float xv = xr[k];
            float4 w = *(const float4*)&sW[k * 192 + j];
            acc.x += xv * w.x; acc.y += xv * w.y;
            acc.z += xv * w.z; acc.w += xv * w.w;
        }
        outr[j4] = acc;
    }
}

// gen: out[row, 0:64]=x@Wsg+bsg, [64:128]=x@Wg2b
__global__ void __launch_bounds__(256) k_gemm_gen(
    const float* __restrict__ xin,
    const float* __restrict__ Wsg, const float* __restrict__ Wg2b,
    const float* __restrict__ bsg)
{
    __shared__ float sW[64 * 128];
    for (int idx = threadIdx.x; idx < 64 * 128; idx += 256) {
        int k = idx / 128, j = idx % 128;
        sW[idx] = (j < 64) ? Wsg[k * 64 + j] : Wg2b[k * 64 + (j - 64)];
    }
    __syncthreads();
    int row = blockIdx.x * 256 + threadIdx.x;
    if (row >= NGS) return;
    const float* xp = xin ? xin : g_hg;
    float xr[64];
    const float4* x4 = (const float4*)(xp + (size_t)row * 64);
#pragma unroll
    for (int i = 0; i < 16; i++) ((float4*)xr)[i] = x4[i];
    float4* outr = (float4*)(g_outg + (size_t)row * 128);
    for (int j4 = 0; j4 < 32; j4++) {
        int j = j4 * 4;
        float4 acc;
        if (j < 64) acc = make_float4(__ldg(&bsg[j]), __ldg(&bsg[j + 1]),
                                      __ldg(&bsg[j + 2]), __ldg(&bsg[j + 3]));
        else acc = make_float4(0.f, 0.f, 0.f, 0.f);
#pragma unroll
        for (int k = 0; k < 64; k++) {
            float xv = xr[k];
            float4 w = *(const float4*)&sW[k * 128 + j];
            acc.x += xv * w.x; acc.y += xv * w.y;
            acc.z += xv * w.z; acc.w += xv * w.w;
        }
        outr[j4] = acc;
    }
}

// ---------------- accumulator clear ----------------
__global__ void k_clear_aggs() {
    int i = blockIdx.x * blockDim.x + threadIdx.x;
    float4 z = make_float4(0.f, 0.f, 0.f, 0.f);
    if (i < NBS * 16) { ((float4*)g_aggL)[i] = z; ((float4*)g_aggG)[i] = z; }
    if (i < NGS * 16) ((float4*)g_aggB)[i] = z;
}

// ---------------- edge scatter (gather at src, vector-RED to dst) ----------------
__global__ void k_scatter(int msg_sel, int stride4, int off4,
                          const int* __restrict__ src, const int* __restrict__ dst,
                          int agg_sel, int nE)
{
    int tid = blockIdx.x * blockDim.x + threadIdx.x;
    int e = tid >> 4;
    if (e >= nE) return;
    int q = tid & 15;
    const float4* msg = (const float4*)((msg_sel == 0) ? g_outb : g_outg);
    float* agg = (agg_sel == 0) ? g_aggL : (agg_sel == 1) ? g_aggG : g_aggB;
    int s = __ldg(&src[e]);
    int d = __ldg(&dst[e]);
    float4 v = msg[(size_t)s * stride4 + off4 + q];
    float* p = agg + (size_t)d * 64 + q * 4;
    asm volatile("red.global.add.v4.f32 [%0], {%1, %2, %3, %4};"
                 :: "l"(p), "f"(v.x), "f"(v.y), "f"(v.z), "f"(v.w) : "memory");
}

// ---------------- combine + ReLU ----------------
__global__ void k_combine_bus() {
    int tid = blockIdx.x * blockDim.x + threadIdx.x;
    int row = tid >> 4;
    if (row >= NBS) return;
    int q = tid & 15;
    float4 s = ((const float4*)g_outb)[(size_t)row * 48 + q];
    float4 a = ((const float4*)g_aggL)[(size_t)row * 16 + q];
    float4 b = ((const float4*)g_aggG)[(size_t)row * 16 + q];
    float il = g_invL[row], ig = g_invG[row];
    float4 r;
    r.x = fmaxf(s.x + a.x * il + b.x * ig, 0.f);
    r.y = fmaxf(s.y + a.y * il + b.y * ig, 0.f);
    r.z = fmaxf(s.z + a.z * il + b.z * ig, 0.f);
    r.w = fmaxf(s.w + a.w * il + b.w * ig, 0.f);
    ((float4*)g_hb)[(size_t)row * 16 + q] = r;
}

__global__ void k_combine_gen() {
    int tid = blockIdx.x * blockDim.x + threadIdx.x;
    int row = tid >> 4;
    if (row >= NGS) return;
    int q = tid & 15;
    float4 s = ((const float4*)g_outg)[(size_t)row * 32 + q];
    float4 a = ((const float4*)g_aggB)[(size_t)row * 16 + q];
    float ib = g_invB[row];
    float4 r;
    r.x = fmaxf(s.x + a.x * ib, 0.f);
    r.y = fmaxf(s.y + a.y * ib, 0.f);
    r.z = fmaxf(s.z + a.z * ib, 0.f);
    r.w = fmaxf(s.w + a.w * ib, 0.f);
    ((float4*)g_hg)[(size_t)row * 16 + q] = r;
}

// ---------------- sum pooling ----------------
__global__ void k_pool(int sel, int n, int obase) {
    const float* h = (sel == 0) ? g_hb : g_hg;
    int col = threadIdx.x & 63, grp = threadIdx.x >> 6;
    float s = 0.f;
    for (int r = blockIdx.x * 4 + grp; r < n; r += gridDim.x * 4)
        s += h[(size_t)r * 64 + col];
    __shared__ float sh[256];
    sh[threadIdx.x] = s;
    __syncthreads();
    if (grp == 0)
        atomicAdd(&g_pool[obase + col],
                  sh[col] + sh[col + 64] + sh[col + 128] + sh[col + 192]);
}

// ---------------- MLP head ----------------
__global__ void k_head(const float* __restrict__ W_h, const float* __restrict__ b_h,
                       const float* __restrict__ W_o, const float* __restrict__ b_o,
                       float* __restrict__ out)
{
    __shared__ float sg[128], st[64];
    int t = threadIdx.x;   // 128 threads
    sg[t] = g_pool[t];
    __syncthreads();
    if (t < 64) {
        float a = b_h[t];
#pragma unroll
        for (int i = 0; i < 128; i++) a += sg[i] * W_h[i * 64 + t];
        st[t] = fmaxf(a, 0.f);
    }
    __syncthreads();
    if (t < 16) {
        float o = b_o[t];
#pragma unroll
        for (int j = 0; j < 64; j++) o += st[j] * W_o[j * 16 + t];
        out[t] = o;
    }
}

// ---------------- launch ----------------
extern "C" void kernel_launch(void* const* d_in, const int* in_sizes, int n_in,
                              void* d_out, int out_size)
{
    const float* x_bus   = (const float*)d_in[0];
    const float* x_gen   = (const float*)d_in[1];
    const int* line_src  = (const int*)d_in[2];
    const int* line_dst  = (const int*)d_in[3];
    const int* g2b_src   = (const int*)d_in[4];
    const int* g2b_dst   = (const int*)d_in[5];
    const int* b2g_src   = (const int*)d_in[6];
    const int* b2g_dst   = (const int*)d_in[7];
    // per layer l: W_self_bus, W_self_gen, W_line, W_g2b, W_b2g, b_self_bus, b_self_gen
    const float* Wsb[2]  = { (const float*)d_in[8],  (const float*)d_in[15] };
    const float* Wsg[2]  = { (const float*)d_in[9],  (const float*)d_in[16] };
    const float* Wl[2]   = { (const float*)d_in[10], (const float*)d_in[17] };
    const float* Wg2b[2] = { (const float*)d_in[11], (const float*)d_in[18] };
    const float* Wb2g[2] = { (const float*)d_in[12], (const float*)d_in[19] };
    const float* bsb[2]  = { (const float*)d_in[13], (const float*)d_in[20] };
    const float* bsg[2]  = { (const float*)d_in[14], (const float*)d_in[21] };
    const float* W_h = (const float*)d_in[22];
    const float* b_h = (const float*)d_in[23];
    const float* W_o = (const float*)d_in[24];
    const float* b_o = (const float*)d_in[25];

    k_zero_init<<<(NBS + 255) / 256, 256>>>();
    k_count<<<(EL + 255) / 256, 256>>>(line_dst, EL, 0);
    k_count<<<(EX + 255) / 256, 256>>>(g2b_dst, EX, 1);
    k_count<<<(EX + 255) / 256, 256>>>(b2g_dst, EX, 2);
    k_inv<<<(NBS + 255) / 256, 256>>>();

    for (int l = 0; l < 2; l++) {
        k_gemm_bus<<<(NBS + 255) / 256, 256>>>(l == 0 ? x_bus : nullptr,
                                               Wsb[l], Wl[l], Wb2g[l], bsb[l]);
        k_gemm_gen<<<(NGS + 255) / 256, 256>>>(l == 0 ? x_gen : nullptr,
                                               Wsg[l], Wg2b[l], bsg[l]);
        k_clear_aggs<<<(NBS * 16 + 255) / 256, 256>>>();
        // line: bus->bus, msg at out_bus cols [64:128) -> aggL
        k_scatter<<<(EL * 16 + 255) / 256, 256>>>(0, 48, 16, line_src, line_dst, 0, EL);
        // g2b: gen->bus, msg at out_gen cols [64:128) -> aggG
        k_scatter<<<(EX * 16 + 255) / 256, 256>>>(1, 32, 16, g2b_src, g2b_dst, 1, EX);
        // b2g: bus->gen, msg at out_bus cols [128:192) -> aggB
        k_scatter<<<(EX * 16 + 255) / 256, 256>>>(0, 48, 32, b2g_src, b2g_dst, 2, EX);
        k_combine_bus<<<(NBS * 16 + 255) / 256, 256>>>();
        k_combine_gen<<<(NGS * 16 + 255) / 256, 256>>>();
    }

    k_pool<<<240, 256>>>(0, NBS, 0);
    k_pool<<<240, 256>>>(1, NGS, 64);
    k_head<<<1, 128>>>(W_h, b_h, W_o, b_o, (float*)d_out);
}

// round 2
// speedup vs baseline: 1.2921x; 1.2921x over previous
#include <cuda_runtime.h>
#include <cuda_bf16.h>

#define NBS 100000
#define NGS 20000
#define EL  1000000
#define EX  200000

// ---------------- scratch (static device globals; no allocation) ----------------
__device__ float g_hb[NBS * 64];
__device__ float g_hg[NGS * 64];
__device__ float g_aggL[NBS * 64];   // sum of hb over line edges, at bus dst
__device__ float g_aggG[NBS * 64];   // sum of hg over g2b edges, at bus dst
__device__ float g_aggB[NGS * 64];   // sum of hb over b2g edges, at gen dst
__device__ float g_invL[NBS], g_invG[NBS], g_invB[NGS];
__device__ int   g_cntL[NBS], g_cntG[NBS], g_cntB[NGS];
__device__ float g_pool[128];

// ---------------- init / counts ----------------
__global__ void k_zero_init() {
    int i = blockIdx.x * blockDim.x + threadIdx.x;
    if (i < NBS) { g_cntL[i] = 0; g_cntG[i] = 0; }
    if (i < NGS) g_cntB[i] = 0;
    if (i < 128) g_pool[i] = 0.f;
}

__global__ void k_count(const int* __restrict__ dst, int n, int sel) {
    int i = blockIdx.x * blockDim.x + threadIdx.x;
    if (i >= n) return;
    int* cnt = (sel == 0) ? g_cntL : (sel == 1) ? g_cntG : g_cntB;
    atomicAdd(&cnt[dst[i]], 1);
}

__global__ void k_inv() {
    int i = blockIdx.x * blockDim.x + threadIdx.x;
    if (i < NBS) {
        g_invL[i] = 1.f / (float)max(g_cntL[i], 1);
        g_invG[i] = 1.f / (float)max(g_cntG[i], 1);
    }
    if (i < NGS) g_invB[i] = 1.f / (float)max(g_cntB[i], 1);
}

// ---------------- accumulator clear ----------------
__global__ void k_clear_aggs() {
    int i = blockIdx.x * blockDim.x + threadIdx.x;
    float4 z = make_float4(0.f, 0.f, 0.f, 0.f);
    if (i < NBS * 16) { ((float4*)g_aggL)[i] = z; ((float4*)g_aggG)[i] = z; }
    if (i < NGS * 16) ((float4*)g_aggB)[i] = z;
}

// ---------------- raw-feature edge scatter ----------------
// Gathers h[src] (64 floats, 16 threads/edge) and vector-REDs into agg[dst].
// h == nullptr selects the internal layer-1 buffers (g_hb / g_hg).
__global__ void k_scatter(const float* h, int hb_sel,
                          const int* __restrict__ src, const int* __restrict__ dst,
                          int agg_sel, int nE)
{
    int tid = blockIdx.x * blockDim.x + threadIdx.x;
    int e = tid >> 4;
    if (e >= nE) return;
    int q = tid & 15;
    const float* hp = h ? h : (hb_sel ? (const float*)g_hb : (const float*)g_hg);
    float* agg = (agg_sel == 0) ? g_aggL : (agg_sel == 1) ? g_aggG : g_aggB;
    int s = __ldg(&src[e]);
    int d = __ldg(&dst[e]);
    float4 v = ((const float4*)hp)[(size_t)s * 16 + q];
    float* p = agg + (size_t)d * 64 + q * 4;
    asm volatile("red.global.add.v4.f32 [%0], {%1, %2, %3, %4};"
                 :: "l"(p), "f"(v.x), "f"(v.y), "f"(v.z), "f"(v.w) : "memory");
}

// ---------------- fused bus update: relu(hb@Wsb + mL@Wl + mG@Wg2b + b) ------------
__global__ void __launch_bounds__(128) k_fused_bus(
    const float* hin,
    const float* __restrict__ Wsb, const float* __restrict__ Wl,
    const float* __restrict__ Wg2b, const float* __restrict__ bsb)
{
    __shared__ float sW[192 * 64];
    __shared__ float sb[64];
    int t = threadIdx.x;
    for (int idx = t; idx < 64 * 64; idx += 128) {
        sW[idx]            = Wsb[idx];
        sW[64 * 64 + idx]  = Wl[idx];
        sW[128 * 64 + idx] = Wg2b[idx];
    }
    if (t < 64) sb[t] = bsb[t];
    __syncthreads();

    int row = blockIdx.x * 128 + t;
    if (row >= NBS) return;
    const float* hp = hin ? hin : (const float*)g_hb;

    float xr[192];
    const float4* a = (const float4*)(hp + (size_t)row * 64);
#pragma unroll
    for (int i = 0; i < 16; i++) ((float4*)xr)[i] = a[i];
    float il = g_invL[row], ig = g_invG[row];
    const float4* pL = (const float4*)(g_aggL + (size_t)row * 64);
    const float4* pG = (const float4*)(g_aggG + (size_t)row * 64);
#pragma unroll
    for (int i = 0; i < 16; i++) {
        float4 v = pL[i];
        v.x *= il; v.y *= il; v.z *= il; v.w *= il;
        ((float4*)xr)[16 + i] = v;
    }
#pragma unroll
    for (int i = 0; i < 16; i++) {
        float4 v = pG[i];
        v.x *= ig; v.y *= ig; v.z *= ig; v.w *= ig;
        ((float4*)xr)[32 + i] = v;
    }

    float4* outr = (float4*)(g_hb + (size_t)row * 64);
    for (int j4 = 0; j4 < 16; j4++) {
        float4 acc = *(const float4*)&sb[j4 * 4];
#pragma unroll
        for (int k = 0; k < 192; k++) {
            float xv = xr[k];
            float4 w = *(const float4*)&sW[k * 64 + j4 * 4];
            acc.x += xv * w.x; acc.y += xv * w.y;
            acc.z += xv * w.z; acc.w += xv * w.w;
        }
        acc.x = fmaxf(acc.x, 0.f); acc.y = fmaxf(acc.y, 0.f);
        acc.z = fmaxf(acc.z, 0.f); acc.w = fmaxf(acc.w, 0.f);
        outr[j4] = acc;
    }
}

// ---------------- fused gen update: relu(hg@Wsg + mB@Wb2g + b) --------------------
__global__ void __launch_bounds__(128) k_fused_gen(
    const float* hin,
    const float* __restrict__ Wsg, const float* __restrict__ Wb2g,
    const float* __restrict__ bsg)
{
    __shared__ float sW[128 * 64];
    __shared__ float sb[64];
    int t = threadIdx.x;
    for (int idx = t; idx < 64 * 64; idx += 128) {
        sW[idx]           = Wsg[idx];
        sW[64 * 64 + idx] = Wb2g[idx];
    }
    if (t < 64) sb[t] = bsg[t];
    __syncthreads();

    int row = blockIdx.x * 128 + t;
    if (row >= NGS) return;
    const float* hp = hin ? hin : (const float*)g_hg;

    float xr[128];
    const float4* a = (const float4*)(hp + (size_t)row * 64);
#pragma unroll
    for (int i = 0; i < 16; i++) ((float4*)xr)[i] = a[i];
    float ib = g_invB[row];
    const float4* pB = (const float4*)(g_aggB + (size_t)row * 64);
#pragma unroll
    for (int i = 0; i < 16; i++) {
        float4 v = pB[i];
        v.x *= ib; v.y *= ib; v.z *= ib; v.w *= ib;
        ((float4*)xr)[16 + i] = v;
    }

    float4* outr = (float4*)(g_hg + (size_t)row * 64);
    for (int j4 = 0; j4 < 16; j4++) {
        float4 acc = *(const float4*)&sb[j4 * 4];
#pragma unroll
        for (int k = 0; k < 128; k++) {
            float xv = xr[k];
            float4 w = *(const float4*)&sW[k * 64 + j4 * 4];
            acc.x += xv * w.x; acc.y += xv * w.y;
            acc.z += xv * w.z; acc.w += xv * w.w;
        }
        acc.x = fmaxf(acc.x, 0.f); acc.y = fmaxf(acc.y, 0.f);
        acc.z = fmaxf(acc.z, 0.f); acc.w = fmaxf(acc.w, 0.f);
        outr[j4] = acc;
    }
}

// ---------------- sum pooling ----------------
__global__ void k_pool(int sel, int n, int obase) {
    const float* h = (sel == 0) ? g_hb : g_hg;
    int col = threadIdx.x & 63, grp = threadIdx.x >> 6;
    float s = 0.f;
    for (int r = blockIdx.x * 4 + grp; r < n; r += gridDim.x * 4)
        s += h[(size_t)r * 64 + col];
    __shared__ float sh[256];
    sh[threadIdx.x] = s;
    __syncthreads();
    if (grp == 0)
        atomicAdd(&g_pool[obase + col],
                  sh[col] + sh[col + 64] + sh[col + 128] + sh[col + 192]);
}

// ---------------- MLP head ----------------
__global__ void k_head(const float* __restrict__ W_h, const float* __restrict__ b_h,
                       const float* __restrict__ W_o, const float* __restrict__ b_o,
                       float* __restrict__ out)
{
    __shared__ float sg[128], st[64];
    int t = threadIdx.x;   // 128 threads
    sg[t] = g_pool[t];
    __syncthreads();
    if (t < 64) {
        float a = b_h[t];
#pragma unroll
        for (int i = 0; i < 128; i++) a += sg[i] * W_h[i * 64 + t];
        st[t] = fmaxf(a, 0.f);
    }
    __syncthreads();
    if (t < 16) {
        float o = b_o[t];
#pragma unroll
        for (int j = 0; j < 64; j++) o += st[j] * W_o[j * 16 + t];
        out[t] = o;
    }
}

// ---------------- launch ----------------
extern "C" void kernel_launch(void* const* d_in, const int* in_sizes, int n_in,
                              void* d_out, int out_size)
{
    const float* x_bus   = (const float*)d_in[0];
    const float* x_gen   = (const float*)d_in[1];
    const int* line_src  = (const int*)d_in[2];
    const int* line_dst  = (const int*)d_in[3];
    const int* g2b_src   = (const int*)d_in[4];
    const int* g2b_dst   = (const int*)d_in[5];
    const int* b2g_src   = (const int*)d_in[6];
    const int* b2g_dst   = (const int*)d_in[7];
    const float* Wsb[2]  = { (const float*)d_in[8],  (const float*)d_in[15] };
    const float* Wsg[2]  = { (const float*)d_in[9],  (const float*)d_in[16] };
    const float* Wl[2]   = { (const float*)d_in[10], (const float*)d_in[17] };
    const float* Wg2b[2] = { (const float*)d_in[11], (const float*)d_in[18] };
    const float* Wb2g[2] = { (const float*)d_in[12], (const float*)d_in[19] };
    const float* bsb[2]  = { (const float*)d_in[13], (const float*)d_in[20] };
    const float* bsg[2]  = { (const float*)d_in[14], (const float*)d_in[21] };
    const float* W_h = (const float*)d_in[22];
    const float* b_h = (const float*)d_in[23];
    const float* W_o = (const float*)d_in[24];
    const float* b_o = (const float*)d_in[25];

    k_zero_init<<<(NBS + 255) / 256, 256>>>();
    k_count<<<(EL + 255) / 256, 256>>>(line_dst, EL, 0);
    k_count<<<(EX + 255) / 256, 256>>>(g2b_dst, EX, 1);
    k_count<<<(EX + 255) / 256, 256>>>(b2g_dst, EX, 2);
    k_inv<<<(NBS + 255) / 256, 256>>>();

    for (int l = 0; l < 2; l++) {
        const float* hb_src = (l == 0) ? x_bus : nullptr;  // nullptr -> g_hb
        const float* hg_src = (l == 0) ? x_gen : nullptr;  // nullptr -> g_hg

        k_clear_aggs<<<(NBS * 16 + 255) / 256, 256>>>();
        // scatter raw features (linearity: apply W after aggregation)
        k_scatter<<<(EL * 16 + 255) / 256, 256>>>(hb_src, 1, line_src, line_dst, 0, EL);
        k_scatter<<<(EX * 16 + 255) / 256, 256>>>(hg_src, 0, g2b_src, g2b_dst, 1, EX);
        k_scatter<<<(EX * 16 + 255) / 256, 256>>>(hb_src, 1, b2g_src, b2g_dst, 2, EX);
        k_fused_bus<<<(NBS + 127) / 128, 128>>>(hb_src, Wsb[l], Wl[l], Wg2b[l], bsb[l]);
        k_fused_gen<<<(NGS + 127) / 128, 128>>>(hg_src, Wsg[l], Wb2g[l], bsg[l]);
    }

    k_pool<<<240, 256>>>(0, NBS, 0);
    k_pool<<<240, 256>>>(1, NGS, 64);
    k_head<<<1, 128>>>(W_h, b_h, W_o, b_o, (float*)d_out);
}

// round 3
// speedup vs baseline: 1.3944x; 1.0792x over previous
#include <cuda_runtime.h>
#include <cstdint>

#define NBS 100000
#define NGS 20000
#define EL  1000000
#define EX  200000

#define BUSB ((NBS + 255) / 256)   // 391
#define GENB ((NGS + 255) / 256)   // 79

// ---------------- scratch (static device globals; no allocation) ----------------
__device__ float g_hb[NBS * 64];
__device__ float g_hg[NGS * 64];
__device__ float g_aggL[NBS * 64];   // sum of hb over line edges, at bus dst
__device__ float g_aggG[NBS * 64];   // sum of hg over g2b edges, at bus dst
__device__ float g_aggB[NGS * 64];   // sum of hb over b2g edges, at gen dst
__device__ float g_invL[NBS], g_invG[NBS], g_invB[NGS];
__device__ int   g_cntL[NBS], g_cntG[NBS], g_cntB[NGS];
__device__ float g_pool[128];

// ---------------- f32x2 helpers ----------------
__device__ __forceinline__ unsigned long long packf2(float v) {
    unsigned long long r;
    asm("mov.b64 %0, {%1, %1};" : "=l"(r) : "f"(v));
    return r;
}
__device__ __forceinline__ unsigned long long packf2b(float a, float b) {
    unsigned long long r;
    asm("mov.b64 %0, {%1, %2};" : "=l"(r) : "f"(a), "f"(b));
    return r;
}
__device__ __forceinline__ void fma2(unsigned long long& acc,
                                     unsigned long long a, unsigned long long b) {
    asm("fma.rn.f32x2 %0, %1, %2, %0;" : "+l"(acc) : "l"(a), "l"(b));
}
__device__ __forceinline__ void lds2(unsigned long long& w0, unsigned long long& w1,
                                     unsigned addr) {
    asm volatile("ld.shared.v2.u64 {%0, %1}, [%2];"
                 : "=l"(w0), "=l"(w1) : "r"(addr));
}
__device__ __forceinline__ void unpackf2(unsigned long long v, float& a, float& b) {
    asm("mov.b64 {%0, %1}, %2;" : "=f"(a), "=f"(b) : "l"(v));
}

// ---------------- init (counts + pool) ----------------
__global__ void k_init() {
    int i = blockIdx.x * blockDim.x + threadIdx.x;
    if (i < NBS) { g_cntL[i] = 0; g_cntG[i] = 0; }
    if (i < NGS) g_cntB[i] = 0;
    if (i < 128) g_pool[i] = 0.f;
}

// ---------------- all in-degree counts in one kernel ----------------
__global__ void k_count_all(const int* __restrict__ ldst,
                            const int* __restrict__ gd,
                            const int* __restrict__ bd) {
    int i = blockIdx.x * blockDim.x + threadIdx.x;
    if (i < EL) atomicAdd(&g_cntL[ldst[i]], 1);
    if (i < EX) { atomicAdd(&g_cntG[gd[i]], 1); atomicAdd(&g_cntB[bd[i]], 1); }
}

__global__ void k_inv() {
    int i = blockIdx.x * blockDim.x + threadIdx.x;
    if (i < NBS) {
        g_invL[i] = 1.f / (float)max(g_cntL[i], 1);
        g_invG[i] = 1.f / (float)max(g_cntG[i], 1);
    }
    if (i < NGS) g_invB[i] = 1.f / (float)max(g_cntB[i], 1);
}

// ---------------- unified raw-feature edge scatter (all 3 edge types) ----------------
// 16 threads/edge: gather h[src] (float4 each) and vector-RED into agg[dst].
// h pointers == nullptr select the internal layer-1 buffers.
__global__ void k_scatter_all(const float* hb, const float* hg,
                              const int* __restrict__ ls, const int* __restrict__ ldst,
                              const int* __restrict__ gs, const int* __restrict__ gd,
                              const int* __restrict__ bs, const int* __restrict__ bd)
{
    int tid = blockIdx.x * 256 + threadIdx.x;
    int e = tid >> 4;
    int q = tid & 15;
    const float* hbp = hb ? hb : (const float*)g_hb;
    const float* hgp = hg ? hg : (const float*)g_hg;

    const float4* srcv;
    float* agg;
    int s, d;
    if (e < EL) {
        s = __ldg(&ls[e]); d = __ldg(&ldst[e]);
        srcv = (const float4*)hbp; agg = g_aggL;
    } else if (e < EL + EX) {
        int e2 = e - EL;
        s = __ldg(&gs[e2]); d = __ldg(&gd[e2]);
        srcv = (const float4*)hgp; agg = g_aggG;
    } else {
        int e2 = e - EL - EX;
        s = __ldg(&bs[e2]); d = __ldg(&bd[e2]);
        srcv = (const float4*)hbp; agg = g_aggB;
    }
    float4 v = srcv[(size_t)s * 16 + q];
    float* p = agg + (size_t)d * 64 + q * 4;
    asm volatile("red.global.add.v4.f32 [%0], {%1, %2, %3, %4};"
                 :: "l"(p), "f"(v.x), "f"(v.y), "f"(v.z), "f"(v.w) : "memory");
}

// ---------------- unified fused update (bus + gen) with f32x2 GEMM ----------------
// bus: new_hb = relu(hb@Wsb + (aggL*invL)@Wl + (aggG*invG)@Wg2b + bsb)
// gen: new_hg = relu(hg@Wsg + (aggB*invB)@Wb2g + bsg)
// Also zeroes the agg rows it consumed (restores invariant for next scatter/call).
__global__ void __launch_bounds__(256) k_fused(
    const float* hbin, const float* hgin,
    const float* __restrict__ Wsb, const float* __restrict__ Wl,
    const float* __restrict__ Wg2b, const float* __restrict__ bsb,
    const float* __restrict__ Wsg, const float* __restrict__ Wb2g,
    const float* __restrict__ bsg)
{
    __shared__ __align__(16) float sW[192 * 64];
    __shared__ __align__(16) float sb[64];
    int t = threadIdx.x;
    bool bus = blockIdx.x < BUSB;

    if (bus) {
        for (int idx = t; idx < 4096; idx += 256) {
            sW[idx]        = Wsb[idx];
            sW[4096 + idx] = Wl[idx];
            sW[8192 + idx] = Wg2b[idx];
        }
        if (t < 64) sb[t] = bsb[t];
    } else {
        for (int idx = t; idx < 4096; idx += 256) {
            sW[idx]        = Wsg[idx];
            sW[4096 + idx] = Wb2g[idx];
        }
        if (t < 64) sb[t] = bsg[t];
    }
    __syncthreads();
    unsigned swb = (unsigned)__cvta_generic_to_shared(sW);

    int row = bus ? blockIdx.x * 256 + t : (blockIdx.x - BUSB) * 256 + t;
    bool valid = row < (bus ? NBS : NGS);
    int r = valid ? row : 0;

    const float* hsrc = bus ? (hbin ? hbin : (const float*)g_hb)
                            : (hgin ? hgin : (const float*)g_hg);
    const float* hp = hsrc + (size_t)r * 64;
    float* agg1 = (bus ? g_aggL : g_aggB) + (size_t)r * 64;
    float* agg2 = g_aggG + (size_t)r * 64;  // only used by bus path
    float sc1 = bus ? g_invL[r] : g_invB[r];
    float sc2 = bus ? g_invG[r] : 0.f;
    int nkc = valid ? (bus ? 6 : 4) : 0;

    unsigned long long acc[32];
#pragma unroll
    for (int g = 0; g < 16; g++) {
        acc[2 * g]     = packf2b(sb[4 * g],     sb[4 * g + 1]);
        acc[2 * g + 1] = packf2b(sb[4 * g + 2], sb[4 * g + 3]);
    }

    for (int kc = 0; kc < nkc; kc++) {
        const float4* s4;
        float sc;
        if (kc < 2)      { s4 = (const float4*)hp   + kc * 8;       sc = 1.f; }
        else if (kc < 4) { s4 = (const float4*)agg1 + (kc - 2) * 8; sc = sc1; }
        else             { s4 = (const float4*)agg2 + (kc - 4) * 8; sc = sc2; }

        float xc[32];
#pragma unroll
        for (int i = 0; i < 8; i++) {
            float4 v = s4[i];
            xc[4 * i]     = v.x * sc;
            xc[4 * i + 1] = v.y * sc;
            xc[4 * i + 2] = v.z * sc;
            xc[4 * i + 3] = v.w * sc;
        }
        unsigned kb = swb + (unsigned)kc * 32 * 256;
#pragma unroll
        for (int kk = 0; kk < 32; kk++) {
            unsigned long long xx = packf2(xc[kk]);
            unsigned a = kb + kk * 256;
#pragma unroll
            for (int g = 0; g < 16; g++) {
                unsigned long long w0, w1;
                lds2(w0, w1, a + g * 16);
                fma2(acc[2 * g],     xx, w0);
                fma2(acc[2 * g + 1], xx, w1);
            }
        }
    }

    if (valid) {
        // restore zeroed aggregation buffers for the next scatter / next call
        float4 z = make_float4(0.f, 0.f, 0.f, 0.f);
        float4* a1 = (float4*)agg1;
#pragma unroll
        for (int i = 0; i < 16; i++) a1[i] = z;
        if (bus) {
            float4* a2 = (float4*)agg2;
#pragma unroll
            for (int i = 0; i < 16; i++) a2[i] = z;
        }
        float* outp = (bus ? g_hb : g_hg) + (size_t)row * 64;
        float4* outr = (float4*)outp;
#pragma unroll
        for (int g = 0; g < 16; g++) {
            float4 o;
            unpackf2(acc[2 * g],     o.x, o.y);
            unpackf2(acc[2 * g + 1], o.z, o.w);
            o.x = fmaxf(o.x, 0.f); o.y = fmaxf(o.y, 0.f);
            o.z = fmaxf(o.z, 0.f); o.w = fmaxf(o.w, 0.f);
            outr[g] = o;
        }
    }
}

// ---------------- sum pooling (bus + gen in one launch) ----------------
__global__ void k_pool_all() {
    bool bus = blockIdx.x < 240;
    const float* h = bus ? g_hb : g_hg;
    int n = bus ? NBS : NGS;
    int obase = bus ? 0 : 64;
    int bid = bus ? blockIdx.x : blockIdx.x - 240;
    int nb  = bus ? 240 : 60;

    int col = threadIdx.x & 63, grp = threadIdx.x >> 6;
    float s = 0.f;
    for (int r = bid * 4 + grp; r < n; r += nb * 4)
        s += h[(size_t)r * 64 + col];
    __shared__ float sh[256];
    sh[threadIdx.x] = s;
    __syncthreads();
    if (grp == 0)
        atomicAdd(&g_pool[obase + col],
                  sh[col] + sh[col + 64] + sh[col + 128] + sh[col + 192]);
}

// ---------------- MLP head ----------------
__global__ void k_head(const float* __restrict__ W_h, const float* __restrict__ b_h,
                       const float* __restrict__ W_o, const float* __restrict__ b_o,
                       float* __restrict__ out)
{
    __shared__ float sg[128], st[64];
    int t = threadIdx.x;   // 128 threads
    sg[t] = g_pool[t];
    __syncthreads();
    if (t < 64) {
        float a = b_h[t];
#pragma unroll
        for (int i = 0; i < 128; i++) a += sg[i] * W_h[i * 64 + t];
        st[t] = fmaxf(a, 0.f);
    }
    __syncthreads();
    if (t < 16) {
        float o = b_o[t];
#pragma unroll
        for (int j = 0; j < 64; j++) o += st[j] * W_o[j * 16 + t];
        out[t] = o;
    }
}

// ---------------- launch ----------------
extern "C" void kernel_launch(void* const* d_in, const int* in_sizes, int n_in,
                              void* d_out, int out_size)
{
    const float* x_bus   = (const float*)d_in[0];
    const float* x_gen   = (const float*)d_in[1];
    const int* line_src  = (const int*)d_in[2];
    const int* line_dst  = (const int*)d_in[3];
    const int* g2b_src   = (const int*)d_in[4];
    const int* g2b_dst   = (const int*)d_in[5];
    const int* b2g_src   = (const int*)d_in[6];
    const int* b2g_dst   = (const int*)d_in[7];
    const float* Wsb[2]  = { (const float*)d_in[8],  (const float*)d_in[15] };
    const float* Wsg[2]  = { (const float*)d_in[9],  (const float*)d_in[16] };
    const float* Wl[2]   = { (const float*)d_in[10], (const float*)d_in[17] };
    const float* Wg2b[2] = { (const float*)d_in[11], (const float*)d_in[18] };
    const float* Wb2g[2] = { (const float*)d_in[12], (const float*)d_in[19] };
    const float* bsb[2]  = { (const float*)d_in[13], (const float*)d_in[20] };
    const float* bsg[2]  = { (const float*)d_in[14], (const float*)d_in[21] };
    const float* W_h = (const float*)d_in[22];
    const float* b_h = (const float*)d_in[23];
    const float* W_o = (const float*)d_in[24];
    const float* b_o = (const float*)d_in[25];

    k_init<<<(NBS + 255) / 256, 256>>>();
    k_count_all<<<(EL + 255) / 256, 256>>>(line_dst, g2b_dst, b2g_dst);
    k_inv<<<(NBS + 255) / 256, 256>>>();

    const int SCAT_BLOCKS = ((EL + 2 * EX) * 16 + 255) / 256;  // 87500
    for (int l = 0; l < 2; l++) {
        const float* hb_src = (l == 0) ? x_bus : nullptr;  // nullptr -> g_hb
        const float* hg_src = (l == 0) ? x_gen : nullptr;  // nullptr -> g_hg
        k_scatter_all<<<SCAT_BLOCKS, 256>>>(hb_src, hg_src,
                                            line_src, line_dst,
                                            g2b_src, g2b_dst,
                                            b2g_src, b2g_dst);
        k_fused<<<BUSB + GENB, 256>>>(hb_src, hg_src,
                                      Wsb[l], Wl[l], Wg2b[l], bsb[l],
                                      Wsg[l], Wb2g[l], bsg[l]);
    }

    k_pool_all<<<300, 256>>>();
    k_head<<<1, 128>>>(W_h, b_h, W_o, b_o, (float*)d_out);
}

// round 4
// speedup vs baseline: 1.4794x; 1.0610x over previous
#include <cuda_runtime.h>
#include <cstdint>

#define NBS 100000
#define NGS 20000
#define EL  1000000
#define EX  200000

#define BUSB ((NBS + 255) / 256)   // 391
#define GENB ((NGS + 255) / 256)   // 79

// ---------------- scratch (static device globals; no allocation) ----------------
__device__ float g_hb[NBS * 64];
__device__ float g_hg[NGS * 64];
__device__ float g_aggL[NBS * 64];   // sum of hb over line edges, at bus dst
__device__ float g_aggG[NBS * 64];   // sum of hg over g2b edges, at bus dst
__device__ float g_aggB[NGS * 64];   // sum of hb over b2g edges, at gen dst
__device__ float g_invL[NBS], g_invG[NBS], g_invB[NGS];
__device__ int   g_cntL[NBS], g_cntG[NBS], g_cntB[NGS];
__device__ float g_pool[128];

// ---------------- f32x2 helpers ----------------
__device__ __forceinline__ unsigned long long packf2(float v) {
    unsigned long long r;
    asm("mov.b64 %0, {%1, %1};" : "=l"(r) : "f"(v));
    return r;
}
__device__ __forceinline__ unsigned long long packf2b(float a, float b) {
    unsigned long long r;
    asm("mov.b64 %0, {%1, %2};" : "=l"(r) : "f"(a), "f"(b));
    return r;
}
__device__ __forceinline__ void fma2(unsigned long long& acc,
                                     unsigned long long a, unsigned long long b) {
    asm("fma.rn.f32x2 %0, %1, %2, %0;" : "+l"(acc) : "l"(a), "l"(b));
}
__device__ __forceinline__ void lds2(unsigned long long& w0, unsigned long long& w1,
                                     unsigned addr) {
    asm volatile("ld.shared.v2.u64 {%0, %1}, [%2];"
                 : "=l"(w0), "=l"(w1) : "r"(addr));
}
__device__ __forceinline__ void unpackf2(unsigned long long v, float& a, float& b) {
    asm("mov.b64 {%0, %1}, %2;" : "=f"(a), "=f"(b) : "l"(v));
}

// ---------------- init (counts + pool) ----------------
__global__ void k_init() {
    int i = blockIdx.x * blockDim.x + threadIdx.x;
    if (i < NBS) { g_cntL[i] = 0; g_cntG[i] = 0; }
    if (i < NGS) g_cntB[i] = 0;
    if (i < 128) g_pool[i] = 0.f;
}

// ---------------- all in-degree counts in one kernel ----------------
__global__ void k_count_all(const int* __restrict__ ldst,
                            const int* __restrict__ gd,
                            const int* __restrict__ bd) {
    int i = blockIdx.x * blockDim.x + threadIdx.x;
    if (i < EL) atomicAdd(&g_cntL[ldst[i]], 1);
    if (i < EX) { atomicAdd(&g_cntG[gd[i]], 1); atomicAdd(&g_cntB[bd[i]], 1); }
}

// split so launch #6 (ncu capture window) is k_fused, not the scatter
__global__ void k_inv_bus() {
    int i = blockIdx.x * blockDim.x + threadIdx.x;
    if (i < NBS) {
        g_invL[i] = 1.f / (float)max(g_cntL[i], 1);
        g_invG[i] = 1.f / (float)max(g_cntG[i], 1);
    }
}
__global__ void k_inv_gen() {
    int i = blockIdx.x * blockDim.x + threadIdx.x;
    if (i < NGS) g_invB[i] = 1.f / (float)max(g_cntB[i], 1);
}

// ---------------- unified raw-feature edge scatter (all 3 edge types) ----------------
// 16 threads/edge: gather h[src] (float4 each) and vector-RED into agg[dst].
// h pointers == nullptr select the internal layer-1 buffers.
__global__ void k_scatter_all(const float* hb, const float* hg,
                              const int* __restrict__ ls, const int* __restrict__ ldst,
                              const int* __restrict__ gs, const int* __restrict__ gd,
                              const int* __restrict__ bs, const int* __restrict__ bd)
{
    int tid = blockIdx.x * 256 + threadIdx.x;
    int e = tid >> 4;
    int q = tid & 15;
    const float* hbp = hb ? hb : (const float*)g_hb;
    const float* hgp = hg ? hg : (const float*)g_hg;

    const float4* srcv;
    float* agg;
    int s, d;
    if (e < EL) {
        s = __ldg(&ls[e]); d = __ldg(&ldst[e]);
        srcv = (const float4*)hbp; agg = g_aggL;
    } else if (e < EL + EX) {
        int e2 = e - EL;
        s = __ldg(&gs[e2]); d = __ldg(&gd[e2]);
        srcv = (const float4*)hgp; agg = g_aggG;
    } else {
        int e2 = e - EL - EX;
        s = __ldg(&bs[e2]); d = __ldg(&bd[e2]);
        srcv = (const float4*)hbp; agg = g_aggB;
    }
    float4 v = srcv[(size_t)s * 16 + q];
    float* p = agg + (size_t)d * 64 + q * 4;
    asm volatile("red.global.add.v4.f32 [%0], {%1, %2, %3, %4};"
                 :: "l"(p), "f"(v.x), "f"(v.y), "f"(v.z), "f"(v.w) : "memory");
}

// ---------------- unified fused update (bus + gen) with f32x2 GEMM ----------------
// bus: new_hb = relu(hb@Wsb + (aggL*invL)@Wl + (aggG*invG)@Wg2b + bsb)
// gen: new_hg = relu(hg@Wsg + (aggB*invB)@Wb2g + bsg)
// Also zeroes the agg rows it consumed (restores invariant for next scatter/call).
// __launch_bounds__(256, 2): force <=128 regs so 2 blocks/SM (4 warps/SMSP) can
// hide the LDS->FFMA2 load-use latency that stalled the 1-block version.
__global__ void __launch_bounds__(256, 2) k_fused(
    const float* hbin, const float* hgin,
    const float* __restrict__ Wsb, const float* __restrict__ Wl,
    const float* __restrict__ Wg2b, const float* __restrict__ bsb,
    const float* __restrict__ Wsg, const float* __restrict__ Wb2g,
    const float* __restrict__ bsg)
{
    __shared__ __align__(16) float sW[192 * 64];
    __shared__ __align__(16) float sb[64];
    int t = threadIdx.x;
    bool bus = blockIdx.x < BUSB;

    if (bus) {
        for (int idx = t; idx < 4096; idx += 256) {
            sW[idx]        = Wsb[idx];
            sW[4096 + idx] = Wl[idx];
            sW[8192 + idx] = Wg2b[idx];
        }
        if (t < 64) sb[t] = bsb[t];
    } else {
        for (int idx = t; idx < 4096; idx += 256) {
            sW[idx]        = Wsg[idx];
            sW[4096 + idx] = Wb2g[idx];
        }
        if (t < 64) sb[t] = bsg[t];
    }
    __syncthreads();
    unsigned swb = (unsigned)__cvta_generic_to_shared(sW);

    int row = bus ? blockIdx.x * 256 + t : (blockIdx.x - BUSB) * 256 + t;
    bool valid = row < (bus ? NBS : NGS);
    int r = valid ? row : 0;

    const float* hsrc = bus ? (hbin ? hbin : (const float*)g_hb)
                            : (hgin ? hgin : (const float*)g_hg);
    const float* hp = hsrc + (size_t)r * 64;
    float* agg1 = (bus ? g_aggL : g_aggB) + (size_t)r * 64;
    float* agg2 = g_aggG + (size_t)r * 64;  // only used by bus path
    float sc1 = bus ? g_invL[r] : g_invB[r];
    float sc2 = bus ? g_invG[r] : 0.f;
    int nkc = valid ? (bus ? 6 : 4) : 0;

    unsigned long long acc[32];
#pragma unroll
    for (int g = 0; g < 16; g++) {
        acc[2 * g]     = packf2b(sb[4 * g],     sb[4 * g + 1]);
        acc[2 * g + 1] = packf2b(sb[4 * g + 2], sb[4 * g + 3]);
    }

    for (int kc = 0; kc < nkc; kc++) {
        const float4* s4;
        float sc;
        if (kc < 2)      { s4 = (const float4*)hp   + kc * 8;       sc = 1.f; }
        else if (kc < 4) { s4 = (const float4*)agg1 + (kc - 2) * 8; sc = sc1; }
        else             { s4 = (const float4*)agg2 + (kc - 4) * 8; sc = sc2; }

        float xc[32];
#pragma unroll
        for (int i = 0; i < 8; i++) {
            float4 v = s4[i];
            xc[4 * i]     = v.x * sc;
            xc[4 * i + 1] = v.y * sc;
            xc[4 * i + 2] = v.z * sc;
            xc[4 * i + 3] = v.w * sc;
        }
        unsigned kb = swb + (unsigned)kc * 32 * 256;
#pragma unroll
        for (int kk = 0; kk < 32; kk++) {
            unsigned long long xx = packf2(xc[kk]);
            unsigned a = kb + kk * 256;
#pragma unroll
            for (int g = 0; g < 16; g++) {
                unsigned long long w0, w1;
                lds2(w0, w1, a + g * 16);
                fma2(acc[2 * g],     xx, w0);
                fma2(acc[2 * g + 1], xx, w1);
            }
        }
    }

    if (valid) {
        // restore zeroed aggregation buffers for the next scatter / next call
        float4 z = make_float4(0.f, 0.f, 0.f, 0.f);
        float4* a1 = (float4*)agg1;
#pragma unroll
        for (int i = 0; i < 16; i++) a1[i] = z;
        if (bus) {
            float4* a2 = (float4*)agg2;
#pragma unroll
            for (int i = 0; i < 16; i++) a2[i] = z;
        }
        float* outp = (bus ? g_hb : g_hg) + (size_t)row * 64;
        float4* outr = (float4*)outp;
#pragma unroll
        for (int g = 0; g < 16; g++) {
            float4 o;
            unpackf2(acc[2 * g],     o.x, o.y);
            unpackf2(acc[2 * g + 1], o.z, o.w);
            o.x = fmaxf(o.x, 0.f); o.y = fmaxf(o.y, 0.f);
            o.z = fmaxf(o.z, 0.f); o.w = fmaxf(o.w, 0.f);
            outr[g] = o;
        }
    }
}

// ---------------- sum pooling (bus + gen in one launch) ----------------
__global__ void k_pool_all() {
    bool bus = blockIdx.x < 240;
    const float* h = bus ? g_hb : g_hg;
    int n = bus ? NBS : NGS;
    int obase = bus ? 0 : 64;
    int bid = bus ? blockIdx.x : blockIdx.x - 240;
    int nb  = bus ? 240 : 60;

    int col = threadIdx.x & 63, grp = threadIdx.x >> 6;
    float s = 0.f;
    for (int r = bid * 4 + grp; r < n; r += nb * 4)
        s += h[(size_t)r * 64 + col];
    __shared__ float sh[256];
    sh[threadIdx.x] = s;
    __syncthreads();
    if (grp == 0)
        atomicAdd(&g_pool[obase + col],
                  sh[col] + sh[col + 64] + sh[col + 128] + sh[col + 192]);
}

// ---------------- MLP head ----------------
__global__ void k_head(const float* __restrict__ W_h, const float* __restrict__ b_h,
                       const float* __restrict__ W_o, const float* __restrict__ b_o,
                       float* __restrict__ out)
{
    __shared__ float sg[128], st[64];
    int t = threadIdx.x;   // 128 threads
    sg[t] = g_pool[t];
    __syncthreads();
    if (t < 64) {
        float a = b_h[t];
#pragma unroll
        for (int i = 0; i < 128; i++) a += sg[i] * W_h[i * 64 + t];
        st[t] = fmaxf(a, 0.f);
    }
    __syncthreads();
    if (t < 16) {
        float o = b_o[t];
#pragma unroll
        for (int j = 0; j < 64; j++) o += st[j] * W_o[j * 16 + t];
        out[t] = o;
    }
}

// ---------------- launch ----------------
extern "C" void kernel_launch(void* const* d_in, const int* in_sizes, int n_in,
                              void* d_out, int out_size)
{
    const float* x_bus   = (const float*)d_in[0];
    const float* x_gen   = (const float*)d_in[1];
    const int* line_src  = (const int*)d_in[2];
    const int* line_dst  = (const int*)d_in[3];
    const int* g2b_src   = (const int*)d_in[4];
    const int* g2b_dst   = (const int*)d_in[5];
    const int* b2g_src   = (const int*)d_in[6];
    const int* b2g_dst   = (const int*)d_in[7];
    const float* Wsb[2]  = { (const float*)d_in[8],  (const float*)d_in[15] };
    const float* Wsg[2]  = { (const float*)d_in[9],  (const float*)d_in[16] };
    const float* Wl[2]   = { (const float*)d_in[10], (const float*)d_in[17] };
    const float* Wg2b[2] = { (const float*)d_in[11], (const float*)d_in[18] };
    const float* Wb2g[2] = { (const float*)d_in[12], (const float*)d_in[19] };
    const float* bsb[2]  = { (const float*)d_in[13], (const float*)d_in[20] };
    const float* bsg[2]  = { (const float*)d_in[14], (const float*)d_in[21] };
    const float* W_h = (const float*)d_in[22];
    const float* b_h = (const float*)d_in[23];
    const float* W_o = (const float*)d_in[24];
    const float* b_o = (const float*)d_in[25];

    k_init<<<(NBS + 255) / 256, 256>>>();                       // 1
    k_count_all<<<(EL + 255) / 256, 256>>>(line_dst, g2b_dst, b2g_dst); // 2
    k_inv_bus<<<(NBS + 255) / 256, 256>>>();                    // 3
    k_inv_gen<<<(NGS + 255) / 256, 256>>>();                    // 4

    const int SCAT_BLOCKS = ((EL + 2 * EX) * 16 + 255) / 256;  // 87500
    for (int l = 0; l < 2; l++) {
        const float* hb_src = (l == 0) ? x_bus : nullptr;  // nullptr -> g_hb
        const float* hg_src = (l == 0) ? x_gen : nullptr;  // nullptr -> g_hg
        k_scatter_all<<<SCAT_BLOCKS, 256>>>(hb_src, hg_src,    // 5 / 7
                                            line_src, line_dst,
                                            g2b_src, g2b_dst,
                                            b2g_src, b2g_dst);
        k_fused<<<BUSB + GENB, 256>>>(hb_src, hg_src,          // 6 (ncu) / 8
                                      Wsb[l], Wl[l], Wg2b[l], bsb[l],
                                      Wsg[l], Wb2g[l], bsg[l]);
    }

    k_pool_all<<<300, 256>>>();
    k_head<<<1, 128>>>(W_h, b_h, W_o, b_o, (float*)d_out);
}